// round 6
// baseline (speedup 1.0000x reference)
#include <cuda_runtime.h>
#include <cuda_bf16.h>
#include <cstdint>

// Block-diagonal equivariant linear, (n,i)-row formulation:
// For block l (d in {1,3,5}, off in {0,128,512}), with r = n*d + i:
//   A[r][u] = x[n][off + u*d + i],  O[r][w] = sum_u A[r][u] * W[u][w] * ALPHA
//   out[n][off + w*d + i] = O[r][w]
// Tiles of 128 r-rows are contiguous in global memory -> coalesced LDG/STG.
// Warp-specialized: 8 consumer warps (ldmatrix + 3-pass hi/lo bf16 MMA),
// 4 producer warps (coalesced load + split to bf16 planes, double buffered).

#define FEATS 1152
#define NT 384
#define NCONS 256
#define NPROD 128
#define PLE 136                      // plane row stride (bf16 elems)
#define PL (128 * PLE * 2)           // plane bytes = 34816
#define SMEM_BYTES (6 * PL)          // 2 bufs x 2 planes + Wh + Wl = 208896
#define OSTRIDE 132                  // fp32 epilogue staging row stride
#define ALPHA_F 0.08838834764831845f // 1/sqrt(128)

__device__ __forceinline__ void mma16816(float* c, const uint32_t* a,
                                         uint32_t b0, uint32_t b1) {
    asm volatile(
        "mma.sync.aligned.m16n8k16.row.col.f32.bf16.bf16.f32 "
        "{%0,%1,%2,%3}, {%4,%5,%6,%7}, {%8,%9}, {%0,%1,%2,%3};"
        : "+f"(c[0]), "+f"(c[1]), "+f"(c[2]), "+f"(c[3])
        : "r"(a[0]), "r"(a[1]), "r"(a[2]), "r"(a[3]), "r"(b0), "r"(b1));
}

__device__ __forceinline__ void ldmx4(uint32_t* r, uint32_t a) {
    asm volatile("ldmatrix.sync.aligned.m8n8.x4.shared.b16 {%0,%1,%2,%3}, [%4];"
                 : "=r"(r[0]), "=r"(r[1]), "=r"(r[2]), "=r"(r[3]) : "r"(a));
}

template <int D, int OFF>
__device__ __forceinline__ void run_block(
    const float* __restrict__ x, const float* __restrict__ w,
    float* __restrict__ out, int ntot, int cidx, int ccnt)
{
    extern __shared__ unsigned char smem[];
    __nv_bfloat16* Wh = reinterpret_cast<__nv_bfloat16*>(smem + 4 * PL);
    __nv_bfloat16* Wl = reinterpret_cast<__nv_bfloat16*>(smem + 5 * PL);
    const int tid = threadIdx.x;
    constexpr int C4 = 32 * D;       // float4 columns per n-row of this block

    // ---- Stage W^T hi/lo (ALPHA folded), once per CTA, all threads ----
    for (int idx = tid; idx < 128 * 128; idx += NT) {
        int u  = idx >> 7;
        int ww = idx & 127;
        float v = w[idx] * ALPHA_F;
        __nv_bfloat16 h = __float2bfloat16(v);
        Wh[ww * PLE + u] = h;
        Wl[ww * PLE + u] = __float2bfloat16(v - __bfloat162float(h));
    }

    const long Rmax = (long)ntot * D;
    const int ntiles = (int)((Rmax + 127) >> 7);

    // ---- Producer: fill bf16 hi/lo planes for one tile (coalesced LDG) ----
    auto fill = [&](int buf, int ktile) {
        __nv_bfloat16* Ah = reinterpret_cast<__nv_bfloat16*>(smem + buf * 2 * PL);
        __nv_bfloat16* Al = reinterpret_cast<__nv_bfloat16*>(smem + buf * 2 * PL + PL);
        const long fr0 = (long)ktile << 7;
        const int fn0 = (int)(fr0 / D);
        long fnh = (fr0 + 127) / D + 1;
        const int fn1 = (int)(fnh < (long)ntot ? fnh : (long)ntot);
        const int ft = (fn1 - fn0) * C4;
        const int p = tid - NCONS;
        for (int t = p; t < ft; t += NPROD) {
            const int nn = fn0 + t / C4;
            const int c4 = t - (t / C4) * C4;
            float4 v = *reinterpret_cast<const float4*>(
                x + (long)nn * FEATS + OFF + 4 * c4);
            float vv[4] = {v.x, v.y, v.z, v.w};
#pragma unroll
            for (int e = 0; e < 4; e++) {
                const int c = 4 * c4 + e;
                const int u = c / D;
                const int ii = c - u * D;
                const int rr = (int)((long)nn * D + ii - fr0);
                if ((unsigned)rr < 128u) {
                    float f = vv[e];
                    __nv_bfloat16 h = __float2bfloat16(f);
                    Ah[rr * PLE + u] = h;
                    Al[rr * PLE + u] = __float2bfloat16(f - __bfloat162float(h));
                }
            }
        }
    };

    // ---- Consumer ldmatrix lane geometry (warp tile m32 x n64, 4m x 2n) ----
    const int warp = tid >> 5;
    const int lane = tid & 31;
    const int m0  = (warp & 3) * 32;
    const int nw0 = (warp >> 2) * 64;
    const int arow = (lane & 7) | (lane & 8);          // A: +8 rows lanes 8-15,24-31
    const int akc  = (lane >> 4) << 3;                 // A: +8 k for lanes 16-31
    const int brow = (lane & 7) | ((lane & 16) >> 1);  // B: +8 rows lanes 16-31
    const int bkc  = lane & 8;                         // B: +8 k for lanes 8-15,24-31
    int aoff[2], boff[4];
#pragma unroll
    for (int mi = 0; mi < 2; mi++)
        aoff[mi] = ((m0 + mi * 16 + arow) * PLE + akc) * 2;
#pragma unroll
    for (int jc = 0; jc < 4; jc++)
        boff[jc] = ((nw0 + jc * 16 + brow) * PLE + bkc) * 2;
    const uint32_t WhS = (uint32_t)__cvta_generic_to_shared(Wh);
    const uint32_t WlS = (uint32_t)__cvta_generic_to_shared(Wl);

    // ---- Prologue: producers fill buffer 0 with first tile ----
    int kt = cidx;
    if (tid >= NCONS && kt < ntiles) fill(0, kt);
    __syncthreads();

    int cur = 0;
    for (; kt < ntiles; kt += ccnt) {
        const long r0 = (long)kt << 7;
        const int n0 = (int)(r0 / D);
        long nh = (r0 + 127) / D + 1;
        const int n1 = (int)(nh < (long)ntot ? nh : (long)ntot);
        const int ntasks = (n1 - n0) * C4;

        float acc[2][8][4];
        if (tid < NCONS) {
            // ---- MMA mainloop on planes[cur] ----
#pragma unroll
            for (int mi = 0; mi < 2; mi++)
#pragma unroll
                for (int j = 0; j < 8; j++)
#pragma unroll
                    for (int r = 0; r < 4; r++) acc[mi][j][r] = 0.0f;

            const uint32_t AhS = (uint32_t)__cvta_generic_to_shared(smem + cur * 2 * PL);
            const uint32_t AlS = AhS + PL;
#pragma unroll
            for (int ks = 0; ks < 8; ks++) {
                const int kb2 = ks * 32;   // 16 bf16 = 32 bytes per k-step
                uint32_t ah[2][4], al[2][4];
                ldmx4(ah[0], AhS + aoff[0] + kb2);
                ldmx4(ah[1], AhS + aoff[1] + kb2);
                ldmx4(al[0], AlS + aoff[0] + kb2);
                ldmx4(al[1], AlS + aoff[1] + kb2);
#pragma unroll
                for (int jc = 0; jc < 4; jc++) {
                    uint32_t bh[4], bl[4];
                    ldmx4(bh, WhS + boff[jc] + kb2);
                    ldmx4(bl, WlS + boff[jc] + kb2);
#pragma unroll
                    for (int mi = 0; mi < 2; mi++) {
                        mma16816(acc[mi][2 * jc],     ah[mi], bh[0], bh[1]); // hi*hi
                        mma16816(acc[mi][2 * jc],     ah[mi], bl[0], bl[1]); // hi*lo
                        mma16816(acc[mi][2 * jc],     al[mi], bh[0], bh[1]); // lo*hi
                        mma16816(acc[mi][2 * jc + 1], ah[mi], bh[2], bh[3]);
                        mma16816(acc[mi][2 * jc + 1], ah[mi], bl[2], bl[3]);
                        mma16816(acc[mi][2 * jc + 1], al[mi], bh[2], bh[3]);
                    }
                }
            }
        } else {
            // ---- Producers: fill other buffer with next tile ----
            int kn = kt + ccnt;
            if (kn < ntiles) fill(cur ^ 1, kn);
        }
        __syncthreads();

        // ---- Epilogue 1: consumers stage acc -> Osm (reuses planes[cur]) ----
        float* Osm = reinterpret_cast<float*>(smem + cur * 2 * PL);
        if (tid < NCONS) {
            const int g = lane >> 2, tq = lane & 3;
#pragma unroll
            for (int mi = 0; mi < 2; mi++) {
#pragma unroll
                for (int j = 0; j < 8; j++) {
                    const int row = m0 + mi * 16 + g;
                    const int col = nw0 + 8 * j + 2 * tq;
                    *reinterpret_cast<float2*>(Osm + row * OSTRIDE + col) =
                        make_float2(acc[mi][j][0], acc[mi][j][1]);
                    *reinterpret_cast<float2*>(Osm + (row + 8) * OSTRIDE + col) =
                        make_float2(acc[mi][j][2], acc[mi][j][3]);
                }
            }
        }
        __syncthreads();

        // ---- Epilogue 2: all threads write Osm -> out, coalesced float4 ----
        for (int t = tid; t < ntasks; t += NT) {
            const int nn = n0 + t / C4;
            const int c4 = t - (t / C4) * C4;
            const long gb = (long)nn * FEATS + OFF + 4 * c4;
            const bool full = ((long)nn * D >= r0) && ((long)(nn + 1) * D <= r0 + 128);
            if (full) {
                float vv[4];
#pragma unroll
                for (int e = 0; e < 4; e++) {
                    const int c = 4 * c4 + e;
                    const int u = c / D;
                    const int ii = c - u * D;
                    const int rr = (int)((long)nn * D + ii - r0);
                    vv[e] = Osm[rr * OSTRIDE + u];
                }
                *reinterpret_cast<float4*>(out + gb) =
                    make_float4(vv[0], vv[1], vv[2], vv[3]);
            } else {
#pragma unroll
                for (int e = 0; e < 4; e++) {
                    const int c = 4 * c4 + e;
                    const int u = c / D;
                    const int ii = c - u * D;
                    const int rr = (int)((long)nn * D + ii - r0);
                    if ((unsigned)rr < 128u)
                        out[gb + e] = Osm[rr * OSTRIDE + u];
                }
            }
        }
        __syncthreads();   // Osm consumed -> producers may refill planes[cur]
        cur ^= 1;
    }
}

__global__ __launch_bounds__(NT, 1)
void Linear_36146444763339_kernel(
    const float* __restrict__ x,
    const float* __restrict__ w0,
    const float* __restrict__ w1,
    const float* __restrict__ w2,
    float* __restrict__ out,
    int ntot)
{
    const int bx = blockIdx.x;
    if (bx < 17)      run_block<1, 0>  (x, w0, out, ntot, bx,      17);
    else if (bx < 66) run_block<3, 128>(x, w1, out, ntot, bx - 17, 49);
    else              run_block<5, 512>(x, w2, out, ntot, bx - 66, 82);
}

extern "C" void kernel_launch(void* const* d_in, const int* in_sizes, int n_in,
                              void* d_out, int out_size) {
    const float* x  = (const float*)d_in[0];
    const float* w0 = (const float*)d_in[1];
    const float* w1 = (const float*)d_in[2];
    const float* w2 = (const float*)d_in[3];
    float* out = (float*)d_out;
    const int ntot = in_sizes[0] / FEATS;

    cudaFuncSetAttribute(Linear_36146444763339_kernel,
                         cudaFuncAttributeMaxDynamicSharedMemorySize, SMEM_BYTES);

    Linear_36146444763339_kernel<<<148, NT, SMEM_BYTES>>>(x, w0, w1, w2, out, ntot);
}

// round 10
// speedup vs baseline: 1.9623x; 1.9623x over previous
#include <cuda_runtime.h>
#include <cuda_bf16.h>
#include <cstdint>

// Block-diagonal equivariant linear, (n,i)-row formulation, mma.sync bf16.
// For block l (d in {1,3,5}, off {0,128,512}), r = n*d + i:
//   A[r][u] = x[n][off+u*d+i];  O[r][w] = sum_u A[r][u]*W[u][w]*ALPHA
// Per 128-row tile: M=N=K=128 GEMM, 3-pass bf16 hi/lo (Ah*Wh + Ah*Wl + Al*Wh),
// fp32 accumulate. A split once at fill time into bf16 hi/lo smem planes
// (double buffered); mainloop is pure ldmatrix + HMMA; epilogue stages through
// smem (overlaying the consumed A buffer) for coalesced float4 stores.

#define FEATS 1152
#define NT 512
#define PLE 136                       // bf16 elems per plane row (pad: ldmatrix-safe)
#define PL  (128 * PLE * 2)           // plane bytes = 34816
#define SMEM_BYTES (6 * PL)           // A: 2 buf x 2 planes; W: 2 planes = 208896
#define OSTRIDE 132
#define ALPHA_F 0.08838834764831845f  // 1/sqrt(128)

__device__ __forceinline__ void mma16816(float* c, const uint32_t* a,
                                         uint32_t b0, uint32_t b1) {
    asm volatile(
        "mma.sync.aligned.m16n8k16.row.col.f32.bf16.bf16.f32 "
        "{%0,%1,%2,%3}, {%4,%5,%6,%7}, {%8,%9}, {%0,%1,%2,%3};"
        : "+f"(c[0]), "+f"(c[1]), "+f"(c[2]), "+f"(c[3])
        : "r"(a[0]), "r"(a[1]), "r"(a[2]), "r"(a[3]), "r"(b0), "r"(b1));
}

__device__ __forceinline__ void ldmx4(uint32_t* r, uint32_t a) {
    asm volatile("ldmatrix.sync.aligned.m8n8.x4.shared.b16 {%0,%1,%2,%3}, [%4];"
                 : "=r"(r[0]), "=r"(r[1]), "=r"(r[2]), "=r"(r[3]) : "r"(a));
}

__device__ __forceinline__ void sts16(uint32_t a, uint32_t v) {
    asm volatile("st.shared.u16 [%0], %1;" :: "r"(a), "r"(v));
}
__device__ __forceinline__ void sts64v(uint32_t a, uint32_t v0, uint32_t v1) {
    asm volatile("st.shared.v2.u32 [%0], {%1,%2};" :: "r"(a), "r"(v0), "r"(v1));
}
// result low16 = bf16_rn(r0), high16 = bf16_rn(r1)
__device__ __forceinline__ uint32_t packbf(float r0, float r1) {
    uint32_t w;
    asm("cvt.rn.satfinite.bf16x2.f32 %0, %1, %2;" : "=r"(w) : "f"(r1), "f"(r0));
    return w;
}

// Fill one A tile: split x into bf16 hi (truncate) / lo (residual, RN) planes.
template <int D, int OFF>
__device__ __forceinline__ void fill_tile(
    uint32_t AhS, const float* __restrict__ x, int ktile, int ntot, int tid)
{
    const int fr0 = ktile << 7;
    const int fn0 = fr0 / D;
    int fn1 = (fr0 + 127) / D + 1; if (fn1 > ntot) fn1 = ntot;
    const int ft = (fn1 - fn0) * 32 * D;
    for (int t = tid; t < ft; t += NT) {
        const int nn = fn0 + t / (32 * D);
        const int c4 = t - (t / (32 * D)) * (32 * D);
        const float4 v = *reinterpret_cast<const float4*>(
            x + (long)nn * FEATS + OFF + 4 * c4);
        if (D == 1) {
            const int rr = nn - fr0;
            uint32_t b0 = __float_as_uint(v.x), b1 = __float_as_uint(v.y);
            uint32_t b2 = __float_as_uint(v.z), b3 = __float_as_uint(v.w);
            float r0f = v.x - __uint_as_float(b0 & 0xFFFF0000u);
            float r1f = v.y - __uint_as_float(b1 & 0xFFFF0000u);
            float r2f = v.z - __uint_as_float(b2 & 0xFFFF0000u);
            float r3f = v.w - __uint_as_float(b3 & 0xFFFF0000u);
            uint32_t a = AhS + (uint32_t)(rr * PLE + 4 * c4) * 2u;
            sts64v(a, __byte_perm(b0, b1, 0x7632), __byte_perm(b2, b3, 0x7632));
            sts64v(a + PL, packbf(r0f, r1f), packbf(r2f, r3f));
        } else {
            const int rr0 = nn * D - fr0;
            const float vv[4] = {v.x, v.y, v.z, v.w};
#pragma unroll
            for (int e = 0; e < 4; e++) {
                const int cc = 4 * c4 + e;
                const int u = cc / D;
                const int rr = rr0 + (cc - u * D);
                if ((unsigned)rr < 128u) {
                    uint32_t fb = __float_as_uint(vv[e]);
                    float res = vv[e] - __uint_as_float(fb & 0xFFFF0000u);
                    uint32_t a = AhS + (uint32_t)(rr * PLE + u) * 2u;
                    sts16(a, fb >> 16);
                    sts16(a + PL, packbf(res, res) & 0xFFFFu);
                }
            }
        }
    }
}

template <int D, int OFF>
__device__ __forceinline__ void run_block(
    const float* __restrict__ x, const float* __restrict__ w,
    float* __restrict__ out, int ntot, int cidx, int ccnt)
{
    extern __shared__ unsigned char smem[];
    const uint32_t smem_u32 = (uint32_t)__cvta_generic_to_shared(smem);
    const uint32_t WhS = smem_u32 + 4 * PL;
    const uint32_t WlS = smem_u32 + 5 * PL;
    __nv_bfloat16* Whp = reinterpret_cast<__nv_bfloat16*>(smem + 4 * PL);
    __nv_bfloat16* Wlp = reinterpret_cast<__nv_bfloat16*>(smem + 5 * PL);
    const int tid = threadIdx.x;

    // ---- Stage W^T hi/lo (ALPHA folded), once per CTA ----
    for (int idx = tid; idx < 128 * 128; idx += NT) {
        int u = idx >> 7, ww = idx & 127;
        float v = w[idx] * ALPHA_F;
        uint32_t fb = __float_as_uint(v);
        float res = v - __uint_as_float(fb & 0xFFFF0000u);
        Whp[ww * PLE + u] = __ushort_as_bfloat16((unsigned short)(fb >> 16));
        Wlp[ww * PLE + u] = __float2bfloat16(res);
    }

    const int ntiles = (ntot * D + 127) >> 7;
    const int nloc = (ntiles - cidx + ccnt - 1) / ccnt;
    if (nloc <= 0) { return; }

    // ---- ldmatrix lane geometry (warp grid 4m x 4n, tile m32 x n32) ----
    const int warp = tid >> 5;
    const int lane = tid & 31;
    const int m0 = (warp & 3) * 32;
    const int n0 = (warp >> 2) * 32;
    const int arow = (lane & 7) | (lane & 8);
    const int akc  = (lane >> 4) << 3;
    const int brow = (lane & 7) | ((lane & 16) >> 1);
    const int bkc  = lane & 8;
    int aoff[2], boff[2];
#pragma unroll
    for (int mi = 0; mi < 2; mi++)
        aoff[mi] = ((m0 + mi * 16 + arow) * PLE + akc) * 2;
#pragma unroll
    for (int jc = 0; jc < 2; jc++)
        boff[jc] = ((n0 + jc * 16 + brow) * PLE + bkc) * 2;

    fill_tile<D, OFF>(smem_u32, x, cidx, ntot, tid);
    __syncthreads();

    float* Osm;
    const int g = lane >> 2, tq = lane & 3;

    for (int j = 0; j < nloc; j++) {
        const int cur = j & 1;
        const uint32_t AhS = smem_u32 + (uint32_t)cur * 2u * PL;

        // ---- Fill next tile into the other buffer (overlaps via 16 warps) ----
        if (j + 1 < nloc)
            fill_tile<D, OFF>(smem_u32 + (uint32_t)(cur ^ 1) * 2u * PL,
                              x, cidx + (j + 1) * ccnt, ntot, tid);

        // ---- MMA mainloop (pure ldmatrix + HMMA) ----
        float acc[2][4][4];
#pragma unroll
        for (int mi = 0; mi < 2; mi++)
#pragma unroll
            for (int jn = 0; jn < 4; jn++)
#pragma unroll
                for (int r = 0; r < 4; r++) acc[mi][jn][r] = 0.0f;

#pragma unroll
        for (int ks = 0; ks < 8; ks++) {
            const int kb2 = ks * 32;
            uint32_t ah[2][4], al[2][4];
            ldmx4(ah[0], AhS + aoff[0] + kb2);
            ldmx4(ah[1], AhS + aoff[1] + kb2);
            ldmx4(al[0], AhS + PL + aoff[0] + kb2);
            ldmx4(al[1], AhS + PL + aoff[1] + kb2);
#pragma unroll
            for (int jc = 0; jc < 2; jc++) {
                uint32_t bh[4], bl[4];
                ldmx4(bh, WhS + boff[jc] + kb2);
                ldmx4(bl, WlS + boff[jc] + kb2);
#pragma unroll
                for (int mi = 0; mi < 2; mi++) {
                    mma16816(acc[mi][2 * jc],     ah[mi], bh[0], bh[1]);
                    mma16816(acc[mi][2 * jc],     ah[mi], bl[0], bl[1]);
                    mma16816(acc[mi][2 * jc],     al[mi], bh[0], bh[1]);
                    mma16816(acc[mi][2 * jc + 1], ah[mi], bh[2], bh[3]);
                    mma16816(acc[mi][2 * jc + 1], ah[mi], bl[2], bl[3]);
                    mma16816(acc[mi][2 * jc + 1], al[mi], bh[2], bh[3]);
                }
            }
        }
        __syncthreads();   // everyone done reading buf cur -> overlay Osm on it

        // ---- Epilogue 1: acc -> Osm[col][row] (transposed, conflict-free) ----
        Osm = reinterpret_cast<float*>(smem + (size_t)cur * 2u * PL);
#pragma unroll
        for (int mi = 0; mi < 2; mi++) {
#pragma unroll
            for (int jn = 0; jn < 4; jn++) {
                const int row = m0 + mi * 16 + g;
                const int col = n0 + 8 * jn + 2 * tq;
                Osm[col * OSTRIDE + row]           = acc[mi][jn][0];
                Osm[(col + 1) * OSTRIDE + row]     = acc[mi][jn][1];
                Osm[col * OSTRIDE + row + 8]       = acc[mi][jn][2];
                Osm[(col + 1) * OSTRIDE + row + 8] = acc[mi][jn][3];
            }
        }
        __syncthreads();

        // ---- Epilogue 2: gather Osm -> coalesced float4 STG in x layout ----
        {
            const int kt = cidx + j * ccnt;
            const int r0 = kt << 7;
            const int en0 = r0 / D;
            int en1 = (r0 + 127) / D + 1; if (en1 > ntot) en1 = ntot;
            const int et = (en1 - en0) * 32 * D;
            for (int t = tid; t < et; t += NT) {
                const int nn = en0 + t / (32 * D);
                const int c4 = t - (t / (32 * D)) * (32 * D);
                const int rr0 = nn * D - r0;
                const bool full = (rr0 >= 0) && (rr0 + D <= 128);
                float vv[4];
#pragma unroll
                for (int e = 0; e < 4; e++) {
                    const int cc = 4 * c4 + e;
                    const int u = cc / D;
                    const int rr = rr0 + (cc - u * D);
                    vv[e] = ((unsigned)rr < 128u) ? Osm[u * OSTRIDE + rr] : 0.0f;
                }
                float* gp = out + (long)nn * FEATS + OFF + 4 * c4;
                if (full) {
                    *reinterpret_cast<float4*>(gp) =
                        make_float4(vv[0], vv[1], vv[2], vv[3]);
                } else {
#pragma unroll
                    for (int e = 0; e < 4; e++) {
                        const int cc = 4 * c4 + e;
                        const int u = cc / D;
                        const int rr = rr0 + (cc - u * D);
                        if ((unsigned)rr < 128u) gp[e] = vv[e];
                    }
                }
            }
        }
        __syncthreads();   // Osm consumed -> next iteration may refill buf cur
    }
}

__global__ __launch_bounds__(NT, 1)
void Linear_36146444763339_kernel(
    const float* __restrict__ x,
    const float* __restrict__ w0,
    const float* __restrict__ w1,
    const float* __restrict__ w2,
    float* __restrict__ out,
    int ntot)
{
    const int bx = blockIdx.x;
    if (bx < 17)      run_block<1, 0>  (x, w0, out, ntot, bx,      17);
    else if (bx < 66) run_block<3, 128>(x, w1, out, ntot, bx - 17, 49);
    else              run_block<5, 512>(x, w2, out, ntot, bx - 66, 82);
}

extern "C" void kernel_launch(void* const* d_in, const int* in_sizes, int n_in,
                              void* d_out, int out_size) {
    const float* x  = (const float*)d_in[0];
    const float* w0 = (const float*)d_in[1];
    const float* w1 = (const float*)d_in[2];
    const float* w2 = (const float*)d_in[3];
    float* out = (float*)d_out;
    const int ntot = in_sizes[0] / FEATS;

    cudaFuncSetAttribute(Linear_36146444763339_kernel,
                         cudaFuncAttributeMaxDynamicSharedMemorySize, SMEM_BYTES);

    Linear_36146444763339_kernel<<<148, NT, SMEM_BYTES>>>(x, w0, w1, w2, out, ntot);
}

// round 12
// speedup vs baseline: 2.1928x; 1.1175x over previous
#include <cuda_runtime.h>
#include <cuda_fp16.h>
#include <cstdint>

// Block-diagonal equivariant linear, (n,i)-row formulation, mma.sync fp16.
// For block l (d in {1,3,5}, off {0,128,512}), r = n*d + i:
//   A[r][u] = x[n][off+u*d+i];  O[r][w] = sum_u A[r][u]*W[u][w]*ALPHA
// Per 128-row tile: M=N=K=128 GEMM.  Precision: A = single fp16 (RN);
// W = fp16 hi + exact-residual fp16 lo (ALPHA folded). 2 passes:
//   acc += A*Wh; acc += A*Wl  ==> A_f16 * W, error ~ 2^-12 (rel ~1e-4).
// fp32 accumulate. A double-buffered; mainloop pure ldmatrix+HMMA; epilogue
// stages through dedicated smem for coalesced float4 stores.

#define FEATS 1152
#define NT 512
#define PLE 136                       // fp16 elems per plane row
#define PL  (128 * PLE * 2)           // plane bytes = 34816
#define OFF_WH (2 * PL)
#define OFF_WL (3 * PL)
#define OFF_OS (4 * PL)               // Osm: 128 cols x 132 rows fp32 = 67584
#define OSTRIDE 132
#define SMEM_BYTES (4 * PL + 128 * OSTRIDE * 4)   // 206848
#define ALPHA_F 0.08838834764831845f  // 1/sqrt(128)

__device__ __forceinline__ void mma16816h(float* c, const uint32_t* a,
                                          uint32_t b0, uint32_t b1) {
    asm volatile(
        "mma.sync.aligned.m16n8k16.row.col.f32.f16.f16.f32 "
        "{%0,%1,%2,%3}, {%4,%5,%6,%7}, {%8,%9}, {%0,%1,%2,%3};"
        : "+f"(c[0]), "+f"(c[1]), "+f"(c[2]), "+f"(c[3])
        : "r"(a[0]), "r"(a[1]), "r"(a[2]), "r"(a[3]), "r"(b0), "r"(b1));
}

__device__ __forceinline__ void ldmx4(uint32_t* r, uint32_t a) {
    asm volatile("ldmatrix.sync.aligned.m8n8.x4.shared.b16 {%0,%1,%2,%3}, [%4];"
                 : "=r"(r[0]), "=r"(r[1]), "=r"(r[2]), "=r"(r[3]) : "r"(a));
}

__device__ __forceinline__ void sts16(uint32_t a, uint32_t v) {
    asm volatile("st.shared.u16 [%0], %1;" :: "r"(a), "r"(v));
}
__device__ __forceinline__ void sts64v(uint32_t a, uint32_t v0, uint32_t v1) {
    asm volatile("st.shared.v2.u32 [%0], {%1,%2};" :: "r"(a), "r"(v0), "r"(v1));
}

// Fill one A tile: x -> single fp16(RN) plane, coalesced float4 LDG.
template <int D, int OFF>
__device__ __forceinline__ void fill_tile(
    uint32_t AS, const float* __restrict__ x, int ktile, int ntot, int tid)
{
    const int fr0 = ktile << 7;
    const int fn0 = fr0 / D;
    int fn1 = (fr0 + 127) / D + 1; if (fn1 > ntot) fn1 = ntot;
    const int ft = (fn1 - fn0) * 32 * D;
    for (int t = tid; t < ft; t += NT) {
        const int nn = fn0 + t / (32 * D);
        const int c4 = t - (t / (32 * D)) * (32 * D);
        const float4 v = *reinterpret_cast<const float4*>(
            x + (long)nn * FEATS + OFF + 4 * c4);
        if (D == 1) {
            const int rr = nn - fr0;
            __half2 h01 = __floats2half2_rn(v.x, v.y);
            __half2 h23 = __floats2half2_rn(v.z, v.w);
            sts64v(AS + (uint32_t)(rr * PLE + 4 * c4) * 2u,
                   *reinterpret_cast<uint32_t*>(&h01),
                   *reinterpret_cast<uint32_t*>(&h23));
        } else {
            const int rr0 = nn * D - fr0;
            const float vv[4] = {v.x, v.y, v.z, v.w};
#pragma unroll
            for (int e = 0; e < 4; e++) {
                const int cc = 4 * c4 + e;
                const int u = cc / D;
                const int rr = rr0 + (cc - u * D);
                if ((unsigned)rr < 128u)
                    sts16(AS + (uint32_t)(rr * PLE + u) * 2u,
                          (uint32_t)__half_as_ushort(__float2half_rn(vv[e])));
            }
        }
    }
}

template <int D, int OFF>
__device__ __forceinline__ void run_block(
    const float* __restrict__ x, const float* __restrict__ w,
    float* __restrict__ out, int ntot, int cidx, int ccnt)
{
    extern __shared__ unsigned char smem[];
    const uint32_t smem_u32 = (uint32_t)__cvta_generic_to_shared(smem);
    const uint32_t WhS = smem_u32 + OFF_WH;
    const uint32_t WlS = smem_u32 + OFF_WL;
    __half* Whp = reinterpret_cast<__half*>(smem + OFF_WH);
    __half* Wlp = reinterpret_cast<__half*>(smem + OFF_WL);
    float* Osm  = reinterpret_cast<float*>(smem + OFF_OS);
    const int tid = threadIdx.x;

    // ---- Stage W^T hi + exact-residual lo (ALPHA folded), once per CTA ----
    for (int idx = tid; idx < 128 * 128; idx += NT) {
        int u = idx >> 7, ww = idx & 127;
        float v = w[idx] * ALPHA_F;
        __half hh = __float2half_rn(v);
        float res = v - __half2float(hh);
        Whp[ww * PLE + u] = hh;
        Wlp[ww * PLE + u] = __float2half_rn(res);
    }

    const int ntiles = (ntot * D + 127) >> 7;
    const int nloc = (ntiles - cidx + ccnt - 1) / ccnt;
    if (nloc <= 0) return;

    // ---- ldmatrix lane geometry (warp grid 4m x 4n, tile m32 x n32) ----
    const int warp = tid >> 5;
    const int lane = tid & 31;
    const int m0 = (warp & 3) * 32;
    const int n0 = (warp >> 2) * 32;
    const int arow = (lane & 7) | (lane & 8);
    const int akc  = (lane >> 4) << 3;
    const int brow = (lane & 7) | ((lane & 16) >> 1);
    const int bkc  = lane & 8;
    int aoff[2], boff[2];
#pragma unroll
    for (int mi = 0; mi < 2; mi++)
        aoff[mi] = ((m0 + mi * 16 + arow) * PLE + akc) * 2;
#pragma unroll
    for (int jc = 0; jc < 2; jc++)
        boff[jc] = ((n0 + jc * 16 + brow) * PLE + bkc) * 2;

    fill_tile<D, OFF>(smem_u32, x, cidx, ntot, tid);
    __syncthreads();

    const int g = lane >> 2, tq = lane & 3;

    for (int j = 0; j < nloc; j++) {
        const uint32_t AS = smem_u32 + (uint32_t)(j & 1) * PL;

        // ---- Fill next tile into the other buffer ----
        if (j + 1 < nloc)
            fill_tile<D, OFF>(smem_u32 + (uint32_t)((j + 1) & 1) * PL,
                              x, cidx + (j + 1) * ccnt, ntot, tid);

        // ---- MMA mainloop: 6 ldmatrix + 16 HMMA per k-step ----
        float acc[2][4][4];
#pragma unroll
        for (int mi = 0; mi < 2; mi++)
#pragma unroll
            for (int jn = 0; jn < 4; jn++)
#pragma unroll
                for (int r = 0; r < 4; r++) acc[mi][jn][r] = 0.0f;

#pragma unroll
        for (int ks = 0; ks < 8; ks++) {
            const int kb2 = ks * 32;
            uint32_t a0[4], a1[4];
            ldmx4(a0, AS + aoff[0] + kb2);
            ldmx4(a1, AS + aoff[1] + kb2);
#pragma unroll
            for (int jc = 0; jc < 2; jc++) {
                uint32_t bh[4], bl[4];
                ldmx4(bh, WhS + boff[jc] + kb2);
                ldmx4(bl, WlS + boff[jc] + kb2);
                mma16816h(acc[0][2 * jc],     a0, bh[0], bh[1]);
                mma16816h(acc[0][2 * jc],     a0, bl[0], bl[1]);
                mma16816h(acc[1][2 * jc],     a1, bh[0], bh[1]);
                mma16816h(acc[1][2 * jc],     a1, bl[0], bl[1]);
                mma16816h(acc[0][2 * jc + 1], a0, bh[2], bh[3]);
                mma16816h(acc[0][2 * jc + 1], a0, bl[2], bl[3]);
                mma16816h(acc[1][2 * jc + 1], a1, bh[2], bh[3]);
                mma16816h(acc[1][2 * jc + 1], a1, bl[2], bl[3]);
            }
        }
        __syncthreads();

        // ---- Epilogue 1: acc -> Osm[col][row] (transposed, conflict-free) ----
#pragma unroll
        for (int mi = 0; mi < 2; mi++) {
#pragma unroll
            for (int jn = 0; jn < 4; jn++) {
                const int row = m0 + mi * 16 + g;
                const int col = n0 + 8 * jn + 2 * tq;
                Osm[col * OSTRIDE + row]           = acc[mi][jn][0];
                Osm[(col + 1) * OSTRIDE + row]     = acc[mi][jn][1];
                Osm[col * OSTRIDE + row + 8]       = acc[mi][jn][2];
                Osm[(col + 1) * OSTRIDE + row + 8] = acc[mi][jn][3];
            }
        }
        __syncthreads();

        // ---- Epilogue 2: gather Osm -> coalesced float4 STG in x layout ----
        {
            const int kt = cidx + j * ccnt;
            const int r0 = kt << 7;
            const int en0 = r0 / D;
            int en1 = (r0 + 127) / D + 1; if (en1 > ntot) en1 = ntot;
            const int et = (en1 - en0) * 32 * D;
            for (int t = tid; t < et; t += NT) {
                const int nn = en0 + t / (32 * D);
                const int c4 = t - (t / (32 * D)) * (32 * D);
                const int rr0 = nn * D - r0;
                const bool full = (rr0 >= 0) && (rr0 + D <= 128);
                float vv[4];
#pragma unroll
                for (int e = 0; e < 4; e++) {
                    const int cc = 4 * c4 + e;
                    const int u = cc / D;
                    const int rr = rr0 + (cc - u * D);
                    vv[e] = ((unsigned)rr < 128u) ? Osm[u * OSTRIDE + rr] : 0.0f;
                }
                float* gp = out + (long)nn * FEATS + OFF + 4 * c4;
                if (full) {
                    *reinterpret_cast<float4*>(gp) =
                        make_float4(vv[0], vv[1], vv[2], vv[3]);
                } else {
#pragma unroll
                    for (int e = 0; e < 4; e++) {
                        const int cc = 4 * c4 + e;
                        const int u = cc / D;
                        const int rr = rr0 + (cc - u * D);
                        if ((unsigned)rr < 128u) gp[e] = vv[e];
                    }
                }
            }
        }
        __syncthreads();   // Osm consumed; A buf (j&1) free for refill next iter
    }
}

__global__ __launch_bounds__(NT, 1)
void Linear_36146444763339_kernel(
    const float* __restrict__ x,
    const float* __restrict__ w0,
    const float* __restrict__ w1,
    const float* __restrict__ w2,
    float* __restrict__ out,
    int ntot)
{
    const int bx = blockIdx.x;
    if (bx < 17)      run_block<1, 0>  (x, w0, out, ntot, bx,      17);
    else if (bx < 66) run_block<3, 128>(x, w1, out, ntot, bx - 17, 49);
    else              run_block<5, 512>(x, w2, out, ntot, bx - 66, 82);
}

extern "C" void kernel_launch(void* const* d_in, const int* in_sizes, int n_in,
                              void* d_out, int out_size) {
    const float* x  = (const float*)d_in[0];
    const float* w0 = (const float*)d_in[1];
    const float* w1 = (const float*)d_in[2];
    const float* w2 = (const float*)d_in[3];
    float* out = (float*)d_out;
    const int ntot = in_sizes[0] / FEATS;

    cudaFuncSetAttribute(Linear_36146444763339_kernel,
                         cudaFuncAttributeMaxDynamicSharedMemorySize, SMEM_BYTES);

    Linear_36146444763339_kernel<<<148, NT, SMEM_BYTES>>>(x, w0, w1, w2, out, ntot);
}

// round 13
// speedup vs baseline: 2.7386x; 1.2489x over previous
#include <cuda_runtime.h>
#include <cuda_fp16.h>
#include <cstdint>

// Block-diagonal equivariant linear, (n,i)-row formulation, mma.sync fp16.
// For block l (d in {1,3,5}, off {0,128,512}), r = n*d + i:
//   A[r][u] = x[n][off+u*d+i];  O[r][w] = sum_u A[r][u]*W[u][w]*ALPHA
// Per 64-row tile: M=64,N=128,K=128 GEMM, single-pass fp16 (A RN, W RN with
// ALPHA folded), fp32 accumulate (rel err ~3e-4 < 1e-3).
// W FRAGMENTS LIVE IN REGISTERS for the whole tile loop (W constant):
// mainloop = 2 ldmatrix + 8 HMMA per k-step per warp. 2 CTAs/SM (256 thr,
// 104KB smem): decoupled barriers. Osm row-major -> vectorized epilogue.

#define FEATS 1152
#define NT 256
#define PLE 136                        // fp16 elems per A-plane row
#define ABUF (64 * PLE * 2)            // one A buffer = 17408 B
#define OFF_WU (2 * ABUF)              // union: W stage (34816 B) / Osm (33792 B)
#define SMEM_BYTES (2 * ABUF + 34816)  // 104448
#define OSTRIDE 132
#define ALPHA_F 0.08838834764831845f   // 1/sqrt(128)

__device__ __forceinline__ void mma16816h(float* c, const uint32_t* a,
                                          uint32_t b0, uint32_t b1) {
    asm volatile(
        "mma.sync.aligned.m16n8k16.row.col.f32.f16.f16.f32 "
        "{%0,%1,%2,%3}, {%4,%5,%6,%7}, {%8,%9}, {%0,%1,%2,%3};"
        : "+f"(c[0]), "+f"(c[1]), "+f"(c[2]), "+f"(c[3])
        : "r"(a[0]), "r"(a[1]), "r"(a[2]), "r"(a[3]), "r"(b0), "r"(b1));
}

__device__ __forceinline__ void ldmx4(uint32_t* r, uint32_t a) {
    asm volatile("ldmatrix.sync.aligned.m8n8.x4.shared.b16 {%0,%1,%2,%3}, [%4];"
                 : "=r"(r[0]), "=r"(r[1]), "=r"(r[2]), "=r"(r[3]) : "r"(a));
}

__device__ __forceinline__ void sts16(uint32_t a, uint32_t v) {
    asm volatile("st.shared.u16 [%0], %1;" :: "r"(a), "r"(v));
}
__device__ __forceinline__ void sts64v(uint32_t a, uint32_t v0, uint32_t v1) {
    asm volatile("st.shared.v2.u32 [%0], {%1,%2};" :: "r"(a), "r"(v0), "r"(v1));
}

// Fill one 64-row A tile: x -> fp16(RN) plane, coalesced float4 LDG.
template <int D, int OFF>
__device__ __forceinline__ void fill_tile(
    uint32_t AS, const float* __restrict__ x, int ktile, int ntot, int tid)
{
    const int fr0 = ktile << 6;
    const int fn0 = fr0 / D;
    int fn1 = (fr0 + 63) / D + 1; if (fn1 > ntot) fn1 = ntot;
    const int ft = (fn1 - fn0) * 32 * D;
    for (int t = tid; t < ft; t += NT) {
        const int nn = fn0 + t / (32 * D);
        const int c4 = t - (t / (32 * D)) * (32 * D);
        const float4 v = *reinterpret_cast<const float4*>(
            x + (long)nn * FEATS + OFF + 4 * c4);
        if (D == 1) {
            const int rr = nn - fr0;
            __half2 h01 = __floats2half2_rn(v.x, v.y);
            __half2 h23 = __floats2half2_rn(v.z, v.w);
            sts64v(AS + (uint32_t)(rr * PLE + 4 * c4) * 2u,
                   *reinterpret_cast<uint32_t*>(&h01),
                   *reinterpret_cast<uint32_t*>(&h23));
        } else {
            const int rr0 = nn * D - fr0;
            const float vv[4] = {v.x, v.y, v.z, v.w};
#pragma unroll
            for (int e = 0; e < 4; e++) {
                const int cc = 4 * c4 + e;
                const int u = cc / D;
                const int rr = rr0 + (cc - u * D);
                if ((unsigned)rr < 64u)
                    sts16(AS + (uint32_t)(rr * PLE + u) * 2u,
                          (uint32_t)__half_as_ushort(__float2half_rn(vv[e])));
            }
        }
    }
}

template <int D, int OFF>
__device__ __forceinline__ void run_block(
    const float* __restrict__ x, const float* __restrict__ w,
    float* __restrict__ out, int ntot, int cidx, int ccnt)
{
    extern __shared__ unsigned char smem[];
    const uint32_t smem_u32 = (uint32_t)__cvta_generic_to_shared(smem);
    const uint32_t WS = smem_u32 + OFF_WU;
    __half* Wp = reinterpret_cast<__half*>(smem + OFF_WU);
    float* Osm = reinterpret_cast<float*>(smem + OFF_WU);
    const int tid = threadIdx.x;

    // ---- Stage W^T fp16 (ALPHA folded) into union region ----
    for (int idx = tid; idx < 128 * 128; idx += NT) {
        int u = idx >> 7, ww = idx & 127;
        Wp[ww * PLE + u] = __float2half_rn(w[idx] * ALPHA_F);
    }
    __syncthreads();

    // ---- Warp geometry (2m x 4n grid, warp tile m32 x n32) ----
    const int warp = tid >> 5;
    const int lane = tid & 31;
    const int m0 = (warp & 1) * 32;
    const int n0 = (warp >> 1) * 32;
    const int arow = (lane & 7) | (lane & 8);
    const int akc  = (lane >> 4) << 3;
    const int brow = (lane & 7) | ((lane & 16) >> 1);
    const int bkc  = lane & 8;
    int aoff[2];
#pragma unroll
    for (int mi = 0; mi < 2; mi++)
        aoff[mi] = ((m0 + mi * 16 + arow) * PLE + akc) * 2;

    // ---- Load ALL W fragments into registers (constant across tiles) ----
    uint32_t wr[64];
#pragma unroll
    for (int ks = 0; ks < 8; ks++)
#pragma unroll
        for (int jc = 0; jc < 2; jc++)
            ldmx4(&wr[ks * 8 + jc * 4],
                  WS + (uint32_t)(((n0 + jc * 16 + brow) * PLE + bkc) * 2 + ks * 32));

    const int ntiles = (ntot * D + 63) >> 6;
    const int nloc = (ntiles - cidx + ccnt - 1) / ccnt;
    if (nloc <= 0) return;

    fill_tile<D, OFF>(smem_u32, x, cidx, ntot, tid);
    __syncthreads();   // fill(0) done; all warps' W-frag ldmatrix done

    const int g = lane >> 2, tq = lane & 3;

    for (int j = 0; j < nloc; j++) {
        const uint32_t AS = smem_u32 + (uint32_t)(j & 1) * ABUF;

        // ---- Fill next tile into the other buffer (overlaps mainloop) ----
        if (j + 1 < nloc)
            fill_tile<D, OFF>(smem_u32 + (uint32_t)((j + 1) & 1) * ABUF,
                              x, cidx + (j + 1) * ccnt, ntot, tid);

        // ---- MMA mainloop: 2 ldmatrix + 8 HMMA per k-step ----
        float acc[2][4][4];
#pragma unroll
        for (int mi = 0; mi < 2; mi++)
#pragma unroll
            for (int jn = 0; jn < 4; jn++)
#pragma unroll
                for (int r = 0; r < 4; r++) acc[mi][jn][r] = 0.0f;

#pragma unroll
        for (int ks = 0; ks < 8; ks++) {
            const int kb2 = ks * 32;
            uint32_t a0[4], a1[4];
            ldmx4(a0, AS + aoff[0] + kb2);
            ldmx4(a1, AS + aoff[1] + kb2);
#pragma unroll
            for (int jc = 0; jc < 2; jc++) {
                const uint32_t* bw = &wr[ks * 8 + jc * 4];
                mma16816h(acc[0][2 * jc],     a0, bw[0], bw[1]);
                mma16816h(acc[1][2 * jc],     a1, bw[0], bw[1]);
                mma16816h(acc[0][2 * jc + 1], a0, bw[2], bw[3]);
                mma16816h(acc[1][2 * jc + 1], a1, bw[2], bw[3]);
            }
        }

        // ---- Epilogue 1: acc -> Osm[row][col] (st.64, no barrier needed:
        //      Osm free since last iter's closing sync) ----
#pragma unroll
        for (int mi = 0; mi < 2; mi++) {
#pragma unroll
            for (int jn = 0; jn < 4; jn++) {
                const int row = m0 + mi * 16 + g;
                const int col = n0 + 8 * jn + 2 * tq;
                *reinterpret_cast<float2*>(Osm + row * OSTRIDE + col) =
                    make_float2(acc[mi][jn][0], acc[mi][jn][1]);
                *reinterpret_cast<float2*>(Osm + (row + 8) * OSTRIDE + col) =
                    make_float2(acc[mi][jn][2], acc[mi][jn][3]);
            }
        }
        __syncthreads();

        // ---- Epilogue 2: Osm -> coalesced float4 STG in x layout ----
        {
            const int kt = cidx + j * ccnt;
            const int r0 = kt << 6;
            const int en0 = r0 / D;
            int en1 = (r0 + 63) / D + 1; if (en1 > ntot) en1 = ntot;
            const int et = (en1 - en0) * 32 * D;
            for (int t = tid; t < et; t += NT) {
                const int nn = en0 + t / (32 * D);
                const int c4 = t - (t / (32 * D)) * (32 * D);
                float* gp = out + (long)nn * FEATS + OFF + 4 * c4;
                if (D == 1) {
                    const int rr = nn - r0;
                    *reinterpret_cast<float4*>(gp) =
                        *reinterpret_cast<const float4*>(Osm + rr * OSTRIDE + 4 * c4);
                } else {
                    const int rr0 = nn * D - r0;
                    const bool full = (rr0 >= 0) && (rr0 + D <= 64);
                    float vv[4];
#pragma unroll
                    for (int e = 0; e < 4; e++) {
                        const int cc = 4 * c4 + e;
                        const int u = cc / D;
                        const int rr = rr0 + (cc - u * D);
                        vv[e] = ((unsigned)rr < 64u) ? Osm[rr * OSTRIDE + u] : 0.0f;
                    }
                    if (full) {
                        *reinterpret_cast<float4*>(gp) =
                            make_float4(vv[0], vv[1], vv[2], vv[3]);
                    } else {
#pragma unroll
                        for (int e = 0; e < 4; e++) {
                            const int cc = 4 * c4 + e;
                            const int u = cc / D;
                            const int rr = rr0 + (cc - u * D);
                            if ((unsigned)rr < 64u) gp[e] = vv[e];
                        }
                    }
                }
            }
        }
        __syncthreads();   // Osm consumed + fill(j+1) visible
    }
}

__global__ __launch_bounds__(NT, 2)
void Linear_36146444763339_kernel(
    const float* __restrict__ x,
    const float* __restrict__ w0,
    const float* __restrict__ w1,
    const float* __restrict__ w2,
    float* __restrict__ out,
    int ntot)
{
    const int bx = blockIdx.x;
    if (bx < 34)       run_block<1, 0>  (x, w0, out, ntot, bx,       34);
    else if (bx < 132) run_block<3, 128>(x, w1, out, ntot, bx - 34,  98);
    else               run_block<5, 512>(x, w2, out, ntot, bx - 132, 164);
}

extern "C" void kernel_launch(void* const* d_in, const int* in_sizes, int n_in,
                              void* d_out, int out_size) {
    const float* x  = (const float*)d_in[0];
    const float* w0 = (const float*)d_in[1];
    const float* w1 = (const float*)d_in[2];
    const float* w2 = (const float*)d_in[3];
    float* out = (float*)d_out;
    const int ntot = in_sizes[0] / FEATS;

    cudaFuncSetAttribute(Linear_36146444763339_kernel,
                         cudaFuncAttributeMaxDynamicSharedMemorySize, SMEM_BYTES);

    Linear_36146444763339_kernel<<<296, NT, SMEM_BYTES>>>(x, w0, w1, w2, out, ntot);
}

// round 14
// speedup vs baseline: 2.7660x; 1.0100x over previous
#include <cuda_runtime.h>
#include <cuda_fp16.h>
#include <cstdint>

// Block-diagonal equivariant linear, (n,i)-row formulation, mma.sync fp16.
// For block l (d in {1,3,5}, off {0,128,512}), r = n*d + i:
//   A[r][u] = x[n][off+u*d+i];  O[r][w] = sum_u A[r][u]*W[u][w]*ALPHA
// Per 64-row tile: M=64,N=128,K=128 GEMM, single-pass fp16 (A RN, W RN with
// ALPHA folded), fp32 accumulate (rel err ~3e-4 < 1e-3).
// W fragments live in registers for the whole tile loop; mainloop is
// 2 ldmatrix + 8 HMMA per k-step per warp.  Epilogue stages the output tile
// in smem in **x-layout** (stage[nnloc][cc], cc = u*D+ii), so the gmem write
// is a pure contiguous float4 copy with no per-element index math.

#define FEATS 1152
#define NT 256
#define PLE 136                        // fp16 elems per A-plane row
#define ABUF (64 * PLE * 2)            // one A buffer = 17408 B
#define OFF_WU (2 * ABUF)              // union: W stage (34816 B) / out stage
#define STAGE_BYTES 36096              // >= max over D of nrows*SN*4, >= W stage
#define SMEM_BYTES (2 * ABUF + STAGE_BYTES)   // 70912
#define ALPHA_F 0.08838834764831845f   // 1/sqrt(128)

__device__ __forceinline__ void mma16816h(float* c, const uint32_t* a,
                                          uint32_t b0, uint32_t b1) {
    asm volatile(
        "mma.sync.aligned.m16n8k16.row.col.f32.f16.f16.f32 "
        "{%0,%1,%2,%3}, {%4,%5,%6,%7}, {%8,%9}, {%0,%1,%2,%3};"
        : "+f"(c[0]), "+f"(c[1]), "+f"(c[2]), "+f"(c[3])
        : "r"(a[0]), "r"(a[1]), "r"(a[2]), "r"(a[3]), "r"(b0), "r"(b1));
}

__device__ __forceinline__ void ldmx4(uint32_t* r, uint32_t a) {
    asm volatile("ldmatrix.sync.aligned.m8n8.x4.shared.b16 {%0,%1,%2,%3}, [%4];"
                 : "=r"(r[0]), "=r"(r[1]), "=r"(r[2]), "=r"(r[3]) : "r"(a));
}

__device__ __forceinline__ void sts16(uint32_t a, uint32_t v) {
    asm volatile("st.shared.u16 [%0], %1;" :: "r"(a), "r"(v));
}
__device__ __forceinline__ void sts64v(uint32_t a, uint32_t v0, uint32_t v1) {
    asm volatile("st.shared.v2.u32 [%0], {%1,%2};" :: "r"(a), "r"(v0), "r"(v1));
}

// Fill one 64-row A tile: x -> fp16(RN) plane, coalesced float4 LDG.
template <int D, int OFF>
__device__ __forceinline__ void fill_tile(
    uint32_t AS, const float* __restrict__ x, int ktile, int ntot, int tid)
{
    const int fr0 = ktile << 6;
    const int fn0 = fr0 / D;
    int fn1 = (fr0 + 63) / D + 1; if (fn1 > ntot) fn1 = ntot;
    const int ft = (fn1 - fn0) * 32 * D;
    for (int t = tid; t < ft; t += NT) {
        const int nn = fn0 + t / (32 * D);
        const int c4 = t - (t / (32 * D)) * (32 * D);
        const float4 v = *reinterpret_cast<const float4*>(
            x + (long)nn * FEATS + OFF + 4 * c4);
        if (D == 1) {
            const int rr = nn - fr0;
            __half2 h01 = __floats2half2_rn(v.x, v.y);
            __half2 h23 = __floats2half2_rn(v.z, v.w);
            sts64v(AS + (uint32_t)(rr * PLE + 4 * c4) * 2u,
                   *reinterpret_cast<uint32_t*>(&h01),
                   *reinterpret_cast<uint32_t*>(&h23));
        } else {
            const int rr0 = nn * D - fr0;
            const float vv[4] = {v.x, v.y, v.z, v.w};
#pragma unroll
            for (int e = 0; e < 4; e++) {
                const int cc = 4 * c4 + e;
                const int u = cc / D;
                const int rr = rr0 + (cc - u * D);
                if ((unsigned)rr < 64u)
                    sts16(AS + (uint32_t)(rr * PLE + u) * 2u,
                          (uint32_t)__half_as_ushort(__float2half_rn(vv[e])));
            }
        }
    }
}

template <int D, int OFF>
__device__ __forceinline__ void run_block(
    const float* __restrict__ x, const float* __restrict__ w,
    float* __restrict__ out, int ntot, int cidx, int ccnt)
{
    constexpr int SN = 128 * D + 4;    // stage floats per n-row (pad rotates banks)
    extern __shared__ unsigned char smem[];
    const uint32_t smem_u32 = (uint32_t)__cvta_generic_to_shared(smem);
    const uint32_t WS = smem_u32 + OFF_WU;
    __half* Wp   = reinterpret_cast<__half*>(smem + OFF_WU);
    float* stage = reinterpret_cast<float*>(smem + OFF_WU);
    const int tid = threadIdx.x;

    // ---- Stage W^T fp16 (ALPHA folded) into union region ----
    for (int idx = tid; idx < 128 * 128; idx += NT) {
        int u = idx >> 7, ww = idx & 127;
        Wp[ww * PLE + u] = __float2half_rn(w[idx] * ALPHA_F);
    }
    __syncthreads();

    // ---- Warp geometry (2m x 4n grid, warp tile m32 x n32) ----
    const int warp = tid >> 5;
    const int lane = tid & 31;
    const int m0 = (warp & 1) * 32;
    const int n0 = (warp >> 1) * 32;
    const int arow = (lane & 7) | (lane & 8);
    const int akc  = (lane >> 4) << 3;
    const int brow = (lane & 7) | ((lane & 16) >> 1);
    const int bkc  = lane & 8;
    int aoff[2];
#pragma unroll
    for (int mi = 0; mi < 2; mi++)
        aoff[mi] = ((m0 + mi * 16 + arow) * PLE + akc) * 2;

    // ---- Load ALL W fragments into registers (constant across tiles) ----
    uint32_t wr[64];
#pragma unroll
    for (int ks = 0; ks < 8; ks++)
#pragma unroll
        for (int jc = 0; jc < 2; jc++)
            ldmx4(&wr[ks * 8 + jc * 4],
                  WS + (uint32_t)(((n0 + jc * 16 + brow) * PLE + bkc) * 2 + ks * 32));

    const int ntiles = (ntot * D + 63) >> 6;
    const int nloc = (ntiles - cidx + ccnt - 1) / ccnt;
    if (nloc <= 0) return;

    fill_tile<D, OFF>(smem_u32, x, cidx, ntot, tid);
    __syncthreads();   // fill(0) done; W-frag ldmatrix done; union now = stage

    const int g = lane >> 2, tq = lane & 3;

    for (int j = 0; j < nloc; j++) {
        const uint32_t AS = smem_u32 + (uint32_t)(j & 1) * ABUF;
        const int kt = cidx + j * ccnt;
        const int r0 = kt << 6;
        const int en0 = r0 / D;
        int en1 = (r0 + 63) / D + 1; if (en1 > ntot) en1 = ntot;

        // ---- Fill next tile into the other buffer (overlaps mainloop) ----
        if (j + 1 < nloc)
            fill_tile<D, OFF>(smem_u32 + (uint32_t)((j + 1) & 1) * ABUF,
                              x, cidx + (j + 1) * ccnt, ntot, tid);

        // ---- MMA mainloop: 2 ldmatrix + 8 HMMA per k-step ----
        float acc[2][4][4];
#pragma unroll
        for (int mi = 0; mi < 2; mi++)
#pragma unroll
            for (int jn = 0; jn < 4; jn++)
#pragma unroll
                for (int r = 0; r < 4; r++) acc[mi][jn][r] = 0.0f;

#pragma unroll
        for (int ks = 0; ks < 8; ks++) {
            const int kb2 = ks * 32;
            uint32_t a0[4], a1[4];
            ldmx4(a0, AS + aoff[0] + kb2);
            ldmx4(a1, AS + aoff[1] + kb2);
#pragma unroll
            for (int jc = 0; jc < 2; jc++) {
                const uint32_t* bw = &wr[ks * 8 + jc * 4];
                mma16816h(acc[0][2 * jc],     a0, bw[0], bw[1]);
                mma16816h(acc[1][2 * jc],     a1, bw[0], bw[1]);
                mma16816h(acc[0][2 * jc + 1], a0, bw[2], bw[3]);
                mma16816h(acc[1][2 * jc + 1], a1, bw[2], bw[3]);
            }
        }

        // ---- Epilogue 1: acc -> stage in x-layout (stage[nnloc][cc]) ----
        // Index math hoisted to 4 divmods per thread per tile.
        // (stage free since last iteration's closing barrier.)
        int rbase[4];
#pragma unroll
        for (int q = 0; q < 4; q++) {
            const int row = m0 + (q >> 1) * 16 + g + (q & 1) * 8;
            const int gr = r0 + row;
            const int nq = gr / D;
            rbase[q] = (nq - en0) * SN + (gr - nq * D);   // nnloc*SN + ii
        }
#pragma unroll
        for (int mi = 0; mi < 2; mi++) {
#pragma unroll
            for (int jn = 0; jn < 4; jn++) {
                const int col = n0 + 8 * jn + 2 * tq;
                if (D == 1) {
                    *reinterpret_cast<float2*>(stage + rbase[2 * mi] + col) =
                        make_float2(acc[mi][jn][0], acc[mi][jn][1]);
                    *reinterpret_cast<float2*>(stage + rbase[2 * mi + 1] + col) =
                        make_float2(acc[mi][jn][2], acc[mi][jn][3]);
                } else {
                    stage[rbase[2 * mi] + col * D]           = acc[mi][jn][0];
                    stage[rbase[2 * mi] + (col + 1) * D]     = acc[mi][jn][1];
                    stage[rbase[2 * mi + 1] + col * D]       = acc[mi][jn][2];
                    stage[rbase[2 * mi + 1] + (col + 1) * D] = acc[mi][jn][3];
                }
            }
        }
        __syncthreads();

        // ---- Epilogue 2: contiguous stage -> gmem float4 copy ----
        {
            const int et = (en1 - en0) * 32 * D;
            for (int t = tid; t < et; t += NT) {
                const int nnr = t / (32 * D);
                const int c4 = t - nnr * (32 * D);
                const int nn = en0 + nnr;
                float* gp = out + (long)nn * FEATS + OFF + 4 * c4;
                const float* sp = stage + nnr * SN + 4 * c4;
                if (D == 1) {
                    *reinterpret_cast<float4*>(gp) =
                        *reinterpret_cast<const float4*>(sp);
                } else {
                    const bool full = (nn * D >= r0) && ((nn + 1) * D <= r0 + 64);
                    if (full) {
                        *reinterpret_cast<float4*>(gp) =
                            *reinterpret_cast<const float4*>(sp);
                    } else {
#pragma unroll
                        for (int e = 0; e < 4; e++) {
                            const int cc = 4 * c4 + e;
                            const int u = cc / D;
                            const int rr = nn * D + (cc - u * D) - r0;
                            if ((unsigned)rr < 64u) gp[e] = sp[e];
                        }
                    }
                }
            }
        }
        __syncthreads();   // stage consumed + fill(j+1) visible
    }
}

__global__ __launch_bounds__(NT, 2)
void Linear_36146444763339_kernel(
    const float* __restrict__ x,
    const float* __restrict__ w0,
    const float* __restrict__ w1,
    const float* __restrict__ w2,
    float* __restrict__ out,
    int ntot)
{
    const int bx = blockIdx.x;
    if (bx < 34)       run_block<1, 0>  (x, w0, out, ntot, bx,       34);
    else if (bx < 132) run_block<3, 128>(x, w1, out, ntot, bx - 34,  98);
    else               run_block<5, 512>(x, w2, out, ntot, bx - 132, 164);
}

extern "C" void kernel_launch(void* const* d_in, const int* in_sizes, int n_in,
                              void* d_out, int out_size) {
    const float* x  = (const float*)d_in[0];
    const float* w0 = (const float*)d_in[1];
    const float* w1 = (const float*)d_in[2];
    const float* w2 = (const float*)d_in[3];
    float* out = (float*)d_out;
    const int ntot = in_sizes[0] / FEATS;

    cudaFuncSetAttribute(Linear_36146444763339_kernel,
                         cudaFuncAttributeMaxDynamicSharedMemorySize, SMEM_BYTES);

    Linear_36146444763339_kernel<<<296, NT, SMEM_BYTES>>>(x, w0, w1, w2, out, ntot);
}